// round 1
// baseline (speedup 1.0000x reference)
#include <cuda_runtime.h>

#define FULL 0xffffffffu

constexpr int NN   = 50000;
constexpr int NE   = 400000;
constexpr int F    = 32;
constexpr int H    = 4;
constexpr int ROWS = NN * H;        // 200000 (n,h) rows
constexpr int NG   = NE / H;        // 100000 message groups (E/H), also E/4 edge groups

// ---- scratch (device globals; no allocation allowed) ----
__device__ float    g_h[ROWS * F];      // current node features (N,H,F)
__device__ float    g_atom[ROWS * F];   // atom_in (N,H,F)
__device__ float    g_xs[ROWS * F];
__device__ float    g_xd[ROWS * F];
__device__ float    g_xm[ROWS * F];
__device__ float    g_exp[NE * H];      // alpha_raw, then exp_a (E,4)
__device__ unsigned g_nmaxu[NN];        // order-encoded float max
__device__ float    g_nsum[NN];
__device__ float    g_aggr[ROWS * F];   // aggr_flat (N*H, F); only slots < NN ever written

__device__ __forceinline__ unsigned fenc(float f) {
    unsigned u = __float_as_uint(f);
    return (u & 0x80000000u) ? ~u : (u | 0x80000000u);
}
__device__ __forceinline__ float fdec(unsigned u) {
    return __uint_as_float((u & 0x80000000u) ? (u & 0x7fffffffu) : ~u);
}

// ---- K0: atom_in = relu(x @ atom_w + atom_b), also h = atom_in ----
// warp per node row; lane covers 4 output cols via float4
__global__ void k_atom(const float* __restrict__ x,
                       const float* __restrict__ w,
                       const float* __restrict__ b) {
    int lane = threadIdx.x & 31;
    int gw = (blockIdx.x * blockDim.x + threadIdx.x) >> 5;
    int nw = (gridDim.x * blockDim.x) >> 5;
    float4 b4 = ((const float4*)b)[lane];
    for (int n = gw; n < NN; n += nw) {
        float4 xv = ((const float4*)x)[n * 32 + lane];
        float4 acc = b4;
#pragma unroll
        for (int k = 0; k < 128; k++) {
            float xk = __shfl_sync(FULL, ((const float*)&xv)[k & 3], k >> 2);
            float4 w4 = ((const float4*)w)[k * 32 + lane];
            acc.x += xk * w4.x; acc.y += xk * w4.y;
            acc.z += xk * w4.z; acc.w += xk * w4.w;
        }
        acc.x = fmaxf(acc.x, 0.f); acc.y = fmaxf(acc.y, 0.f);
        acc.z = fmaxf(acc.z, 0.f); acc.w = fmaxf(acc.w, 0.f);
        ((float4*)g_atom)[n * 32 + lane] = acc;
        ((float4*)g_h)[n * 32 + lane]   = acc;
    }
}

// ---- K1: out = g_h @ W + b for each (n,h) row; sel picks xs/xd/xm ----
__global__ void k_nlin(const float* __restrict__ w,
                       const float* __restrict__ b, int sel) {
    int lane = threadIdx.x & 31;
    float wr[32];
#pragma unroll
    for (int k = 0; k < 32; k++) wr[k] = w[k * 32 + lane];
    float bf = b[lane];
    float* out = (sel == 0) ? g_xs : (sel == 1) ? g_xd : g_xm;
    int gw = (blockIdx.x * blockDim.x + threadIdx.x) >> 5;
    int nw = (gridDim.x * blockDim.x) >> 5;
    for (int r = gw; r < ROWS; r += nw) {
        float hv = g_h[r * 32 + lane];
        float acc = bf;
#pragma unroll
        for (int k = 0; k < 32; k++)
            acc += __shfl_sync(FULL, hv, k) * wr[k];
        out[r * 32 + lane] = acc;
    }
}

// ---- K2: zero aggr/nsum, init nmax to encoded -inf ----
__global__ void k_init() {
    int i = blockIdx.x * blockDim.x + threadIdx.x;
    int stride = gridDim.x * blockDim.x;
    for (int j = i; j < ROWS * F / 4; j += stride)
        ((float4*)g_aggr)[j] = make_float4(0.f, 0.f, 0.f, 0.f);
    for (int j = i; j < NN; j += stride) {
        g_nsum[j]  = 0.f;
        g_nmaxu[j] = 0x007FFFFFu;   // fenc(-inf)
    }
}

// ---- K3: edge attention: alpha_raw + segment max ----
// warp per edge; fuses ea = edge_attr @ aew + aeb
__global__ void k_attn(const float* __restrict__ eattr, const int* __restrict__ ei,
                       const float* __restrict__ w,  const float* __restrict__ b,
                       const float* __restrict__ dw, const float* __restrict__ db) {
    int lane = threadIdx.x & 31;
    float wr[32];
#pragma unroll
    for (int k = 0; k < 32; k++) wr[k] = w[k * 32 + lane];
    float bf = b[lane];
    float dwf = dw[lane];
    float dbv = db[0];
    int gw = (blockIdx.x * blockDim.x + threadIdx.x) >> 5;
    int nw = (gridDim.x * blockDim.x) >> 5;
    for (int e = gw; e < NE; e += nw) {
        int s = ei[e];
        int d = ei[NE + e];
        float ev = eattr[e * 32 + lane];
        float ea = bf;
#pragma unroll
        for (int k = 0; k < 32; k++)
            ea += __shfl_sync(FULL, ev, k) * wr[k];
        float ar[4];
        float m = -3.4e38f;
#pragma unroll
        for (int h = 0; h < 4; h++) {
            float v = g_xs[d * 128 + h * 32 + lane] +
                      g_xd[s * 128 + h * 32 + lane] + ea;
            v = fmaxf(v, 0.f) * dwf;
#pragma unroll
            for (int o = 16; o; o >>= 1)
                v += __shfl_xor_sync(FULL, v, o);
            v += dbv;
            ar[h] = v;
            m = fmaxf(m, v);
        }
        if (lane == 0) {
            ((float4*)g_exp)[e] = make_float4(ar[0], ar[1], ar[2], ar[3]);
            atomicMax(&g_nmaxu[d], fenc(m));
        }
    }
}

// ---- K4: exp + segment sum ----
__global__ void k_exp(const int* __restrict__ ei) {
    int e = blockIdx.x * blockDim.x + threadIdx.x;
    if (e >= NE) return;
    int d = ei[NE + e];
    float nm = fdec(g_nmaxu[d]);
    float4 a = ((float4*)g_exp)[e];
    a.x = expf(a.x - nm); a.y = expf(a.y - nm);
    a.z = expf(a.z - nm); a.w = expf(a.w - nm);
    ((float4*)g_exp)[e] = a;
    atomicAdd(&g_nsum[d], a.x + a.y + a.z + a.w);
}

// ---- K5: messages + tiled scatter ----
// Reference scatters msg_flat[m] (m=(e,h), row e*H+h) to segment dst[m mod E].
// Since E % H == 0, contributions m = c*E + r for c=0..3 all land on dst[r],
// with source (e', h') = (c*(E/H) + r/4, r%4). One warp handles group g = r/4:
// it sums the 4 tile copies and issues 4 vector REDs (one per j = r%4).
__global__ void k_msg(const float* __restrict__ eattr, const int* __restrict__ ei,
                      const float* __restrict__ w, const float* __restrict__ b) {
    __shared__ float sT[8][128];
    int lane = threadIdx.x & 31;
    int wib = threadIdx.x >> 5;
    float wr[32];
#pragma unroll
    for (int k = 0; k < 32; k++) wr[k] = w[k * 32 + lane];
    float bf = b[lane];
    int gw = (blockIdx.x * blockDim.x + threadIdx.x) >> 5;
    int nw = (gridDim.x * blockDim.x) >> 5;
    for (int g = gw; g < NG; g += nw) {
        float T0 = 0.f, T1 = 0.f, T2 = 0.f, T3 = 0.f;
#pragma unroll
        for (int c = 0; c < 4; c++) {
            int e = c * NG + g;
            int d = ei[NE + e];
            float4 ex = ((const float4*)g_exp)[e];
            float inv = 1.f / (g_nsum[d] + 1e-8f);
            float ev = eattr[e * 32 + lane];
            float em = bf;
#pragma unroll
            for (int k = 0; k < 32; k++)
                em += __shfl_sync(FULL, ev, k) * wr[k];
            const float* xp = g_xm + d * 128;
            T0 += (ex.x * inv) * (xp[lane]      + em);
            T1 += (ex.y * inv) * (xp[32 + lane] + em);
            T2 += (ex.z * inv) * (xp[64 + lane] + em);
            T3 += (ex.w * inv) * (xp[96 + lane] + em);
        }
        sT[wib][lane]      = T0;
        sT[wib][32 + lane] = T1;
        sT[wib][64 + lane] = T2;
        sT[wib][96 + lane] = T3;
        __syncwarp();
        int j  = lane >> 3;
        int f4 = lane & 7;
        float4 v = *(const float4*)&sT[wib][j * 32 + f4 * 4];
        int tgt = ei[NE + 4 * g + j];
        float* p = g_aggr + (size_t)tgt * 32 + f4 * 4;
        asm volatile("red.global.add.v4.f32 [%0], {%1,%2,%3,%4};"
                     :: "l"(p), "f"(v.x), "f"(v.y), "f"(v.z), "f"(v.w)
                     : "memory");
        __syncwarp();
    }
}

// ---- K6: h = relu(aggr + h @ wnw + wnb + atom_in) ----
__global__ void k_comb(const float* __restrict__ w, const float* __restrict__ b) {
    int lane = threadIdx.x & 31;
    float wr[32];
#pragma unroll
    for (int k = 0; k < 32; k++) wr[k] = w[k * 32 + lane];
    float bf = b[lane];
    int gw = (blockIdx.x * blockDim.x + threadIdx.x) >> 5;
    int nw = (gridDim.x * blockDim.x) >> 5;
    for (int r = gw; r < ROWS; r += nw) {
        float hv = g_h[r * 32 + lane];
        float acc = bf;
#pragma unroll
        for (int k = 0; k < 32; k++)
            acc += __shfl_sync(FULL, hv, k) * wr[k];
        float v = g_aggr[r * 32 + lane] + acc + g_atom[r * 32 + lane];
        g_h[r * 32 + lane] = fmaxf(v, 0.f);
    }
}

// ---- K7: out[n,f] = mean over heads ----
__global__ void k_mean(float* __restrict__ out) {
    int i = blockIdx.x * blockDim.x + threadIdx.x;
    if (i >= NN * F) return;
    int n = i >> 5;
    int f = i & 31;
    const float* p = g_h + n * 128 + f;
    out[i] = 0.25f * (p[0] + p[32] + p[64] + p[96]);
}

extern "C" void kernel_launch(void* const* d_in, const int* in_sizes, int n_in,
                              void* d_out, int out_size) {
    const float* x      = (const float*)d_in[0];
    const float* eattr  = (const float*)d_in[1];
    const int*   ei     = (const int*)d_in[2];
    const float* atom_w = (const float*)d_in[3];
    const float* atom_b = (const float*)d_in[4];
    const float* asw  = (const float*)d_in[5];
    const float* asb  = (const float*)d_in[6];
    const float* adw  = (const float*)d_in[7];
    const float* adb  = (const float*)d_in[8];
    const float* aew  = (const float*)d_in[9];
    const float* aeb  = (const float*)d_in[10];
    const float* dotw = (const float*)d_in[11];
    const float* dotb = (const float*)d_in[12];
    const float* mdw  = (const float*)d_in[13];
    const float* mdb  = (const float*)d_in[14];
    const float* mew  = (const float*)d_in[15];
    const float* meb  = (const float*)d_in[16];
    const float* wnw  = (const float*)d_in[17];
    const float* wnb  = (const float*)d_in[18];
    float* out = (float*)d_out;

    k_atom<<<512, 256>>>(x, atom_w, atom_b);
    for (int l = 0; l < 2; l++) {
        int wo = l * 32 * 32, bo = l * 32;
        k_nlin<<<1024, 256>>>(asw + wo, asb + bo, 0);
        k_nlin<<<1024, 256>>>(adw + wo, adb + bo, 1);
        k_nlin<<<1024, 256>>>(mdw + wo, mdb + bo, 2);
        k_init<<<512, 256>>>();
        k_attn<<<1024, 256>>>(eattr, ei, aew + wo, aeb + bo, dotw + l * 32, dotb + l);
        k_exp<<<(NE + 255) / 256, 256>>>(ei);
        k_msg<<<1024, 256>>>(eattr, ei, mew + wo, meb + bo);
        k_comb<<<1024, 256>>>(wnw + wo, wnb + bo);
    }
    k_mean<<<(NN * F + 255) / 256, 256>>>(out);
}